// round 5
// baseline (speedup 1.0000x reference)
#include <cuda_runtime.h>

#define FDIM 64
#define WIN  16
#define BT   96
#define ROWS (BT + WIN - 1)   /* 111 */
#define NEG  0.2f

__global__ __launch_bounds__(256, 3)
void gat_kernel(const float* __restrict__ ori,
                const float* __restrict__ Wfc,
                const float* __restrict__ attn_l,
                const float* __restrict__ attn_r,
                const float* __restrict__ bias,
                float* __restrict__ out, int T)
{
    __shared__ __align__(16) float Wsh[FDIM][FDIM];   // [k][c]
    __shared__ __align__(16) float zsh[ROWS][FDIM];   // x tile, overwritten by z in place
    __shared__ __align__(16) float alsh[FDIM];
    __shared__ __align__(16) float arsh[FDIM];
    __shared__ __align__(16) float bsh[FDIM];
    __shared__ __align__(16) float elsh[ROWS];
    __shared__ __align__(16) float ersh[ROWS];

    const int tid = threadIdx.x;
    const int t0  = blockIdx.x * BT;

    // ---- stage W_fc (row-major [k][c]) ----
    for (int i = tid; i < FDIM * FDIM / 4; i += 256)
        ((float4*)Wsh)[i] = ((const float4*)Wfc)[i];
    if (tid < FDIM) {
        alsh[tid] = attn_l[tid];
        arsh[tid] = attn_r[tid];
        bsh[tid]  = bias[tid];
    }
    // ---- stage input rows [t0-15 .. t0+BT-1], clamped (left-pad semantics) ----
    for (int i = tid; i < ROWS * (FDIM / 4); i += 256) {
        int r  = i >> 4;
        int c4 = i & 15;
        int s  = t0 - (WIN - 1) + r;
        s = s < 0 ? 0 : (s > T - 1 ? T - 1 : s);
        ((float4*)zsh[r])[c4] = ((const float4*)(ori + (size_t)s * FDIM))[c4];
    }
    __syncthreads();

    // ---- GEMM: z[r][c] = sum_k x[r][k]*W[k][c]
    // 8 rows/warp-iter, 2 cols/lane; k unrolled by 4 with broadcast LDS.128 x-loads
    const int warp = tid >> 5, lane = tid & 31;
    const float2 alv = *(const float2*)&alsh[2 * lane];
    const float2 arv = *(const float2*)&arsh[2 * lane];

    for (int base = warp * 8; base < ROWS; base += 64) {
        int ri[8];
        #pragma unroll
        for (int i = 0; i < 8; i++) {
            int rr = base + i;
            ri[i] = rr < ROWS ? rr : ROWS - 1;   // clamped rows: results discarded
        }
        float acc[8][2];
        #pragma unroll
        for (int i = 0; i < 8; i++) { acc[i][0] = 0.f; acc[i][1] = 0.f; }

        #pragma unroll
        for (int k4 = 0; k4 < FDIM / 4; k4++) {
            float2 wv0 = *(const float2*)&Wsh[4*k4 + 0][2 * lane];
            float2 wv1 = *(const float2*)&Wsh[4*k4 + 1][2 * lane];
            float2 wv2 = *(const float2*)&Wsh[4*k4 + 2][2 * lane];
            float2 wv3 = *(const float2*)&Wsh[4*k4 + 3][2 * lane];
            #pragma unroll
            for (int i = 0; i < 8; i++) {
                float4 xv = *(const float4*)&zsh[ri[i]][4 * k4];  // broadcast LDS.128
                acc[i][0] += xv.x * wv0.x;  acc[i][1] += xv.x * wv0.y;
                acc[i][0] += xv.y * wv1.x;  acc[i][1] += xv.y * wv1.y;
                acc[i][0] += xv.z * wv2.x;  acc[i][1] += xv.z * wv2.y;
                acc[i][0] += xv.w * wv3.x;  acc[i][1] += xv.w * wv3.y;
            }
        }
        // in-place z write: this warp is the only reader/writer of its rows;
        // clamped-row reads by other warps feed only discarded accumulators
        #pragma unroll
        for (int i = 0; i < 8; i++) {
            int rr = base + i;
            if (rr < ROWS)
                *(float2*)&zsh[rr][2 * lane] = make_float2(acc[i][0], acc[i][1]);
        }
        // el/er per row via butterfly reduction
        float el[8], er[8];
        #pragma unroll
        for (int i = 0; i < 8; i++) {
            el[i] = acc[i][0] * alv.x + acc[i][1] * alv.y;
            er[i] = acc[i][0] * arv.x + acc[i][1] * arv.y;
        }
        #pragma unroll
        for (int off = 16; off; off >>= 1) {
            #pragma unroll
            for (int i = 0; i < 8; i++) {
                el[i] += __shfl_xor_sync(0xffffffffu, el[i], off);
                er[i] += __shfl_xor_sync(0xffffffffu, er[i], off);
            }
        }
        if (lane == 0) {
            #pragma unroll
            for (int i = 0; i < 8; i++) {
                int rr = base + i;
                if (rr < ROWS) { elsh[rr] = el[i]; ersh[rr] = er[i]; }
            }
        }
    }
    __syncthreads();

    // ---- attention: dst = last window slot; softmax over 16 src rows ----
    const int g  = tid >> 4;   // 16 groups of 16 lanes
    const int gl = tid & 15;
    const float4 bv = *(const float4*)&bsh[4 * gl];

    for (int j = g; j < BT; j += 16) {
        int t = t0 + j;
        if (t >= T) break;
        float ert = ersh[j + WIN - 1];
        float ew[WIN];
        float m = -1e30f;
        #pragma unroll
        for (int u = 0; u < WIN; u++) {
            float e = elsh[j + u] + ert;
            e = (e > 0.f) ? e : NEG * e;
            ew[u] = e;
            m = fmaxf(m, e);
        }
        float ssum = 0.f;
        #pragma unroll
        for (int u = 0; u < WIN; u++) {
            float x = __expf(ew[u] - m);
            ew[u] = x;
            ssum += x;
        }
        float inv = 1.f / ssum;
        float4 acc = make_float4(0.f, 0.f, 0.f, 0.f);
        #pragma unroll
        for (int u = 0; u < WIN; u++) {
            float4 zv = *(const float4*)&zsh[j + u][4 * gl];
            float w = ew[u];
            acc.x += w * zv.x; acc.y += w * zv.y;
            acc.z += w * zv.z; acc.w += w * zv.w;
        }
        float4 o;
        o.x = acc.x * inv + bv.x;
        o.y = acc.y * inv + bv.y;
        o.z = acc.z * inv + bv.z;
        o.w = acc.w * inv + bv.w;
        *(float4*)&out[(size_t)t * FDIM + 4 * gl] = o;
    }
}

extern "C" void kernel_launch(void* const* d_in, const int* in_sizes, int n_in,
                              void* d_out, int out_size) {
    const float* ori    = (const float*)d_in[0];
    const float* Wfc    = (const float*)d_in[1];
    const float* attn_l = (const float*)d_in[2];
    const float* attn_r = (const float*)d_in[3];
    const float* bias   = (const float*)d_in[4];
    float* out = (float*)d_out;
    int T = in_sizes[0] / FDIM;
    int grid = (T + BT - 1) / BT;
    gat_kernel<<<grid, 256>>>(ori, Wfc, attn_l, attn_r, bias, out, T);
}

// round 6
// speedup vs baseline: 1.0579x; 1.0579x over previous
#include <cuda_runtime.h>

#define FDIM 64
#define WIN  16
#define BT   96
#define ROWS (BT + WIN - 1)   /* 111 */
#define NEG  0.2f

__global__ __launch_bounds__(256, 3)
void gat_kernel(const float* __restrict__ ori,
                const float* __restrict__ Wfc,
                const float* __restrict__ attn_l,
                const float* __restrict__ attn_r,
                const float* __restrict__ bias,
                float* __restrict__ out, int T)
{
    __shared__ __align__(16) float Wsh[FDIM][FDIM];   // [k][c]
    __shared__ __align__(16) float zsh[ROWS][FDIM];   // x tile, overwritten by z in place
    __shared__ __align__(16) float alsh[FDIM];
    __shared__ __align__(16) float arsh[FDIM];
    __shared__ __align__(16) float bsh[FDIM];
    __shared__ __align__(16) float elsh[ROWS];
    __shared__ __align__(16) float ersh[ROWS];

    const int tid = threadIdx.x;
    const int t0  = blockIdx.x * BT;

    // ---- stage W_fc (row-major [k][c]) ----
    for (int i = tid; i < FDIM * FDIM / 4; i += 256)
        ((float4*)Wsh)[i] = ((const float4*)Wfc)[i];
    if (tid < FDIM) {
        alsh[tid] = attn_l[tid];
        arsh[tid] = attn_r[tid];
        bsh[tid]  = bias[tid];
    }
    // ---- stage input rows [t0-15 .. t0+BT-1], clamped (left-pad semantics) ----
    for (int i = tid; i < ROWS * (FDIM / 4); i += 256) {
        int r  = i >> 4;
        int c4 = i & 15;
        int s  = t0 - (WIN - 1) + r;
        s = s < 0 ? 0 : (s > T - 1 ? T - 1 : s);
        ((float4*)zsh[r])[c4] = ((const float4*)(ori + (size_t)s * FDIM))[c4];
    }
    __syncthreads();

    // ---- GEMM: z[r][c] = sum_k x[r][k]*W[k][c]
    // 4 rows/warp-iter (register-budget-safe), 2 cols/lane,
    // k unrolled by 4 with broadcast LDS.128 x-loads
    const int warp = tid >> 5, lane = tid & 31;
    const float2 alv = *(const float2*)&alsh[2 * lane];
    const float2 arv = *(const float2*)&arsh[2 * lane];

    for (int base = warp * 4; base < ROWS; base += 32) {
        const float* rp[4];
        #pragma unroll
        for (int i = 0; i < 4; i++) {
            int rr = base + i;
            rp[i] = zsh[rr < ROWS ? rr : ROWS - 1];   // clamped rows: results discarded
        }
        float acc[4][2];
        #pragma unroll
        for (int i = 0; i < 4; i++) { acc[i][0] = 0.f; acc[i][1] = 0.f; }

        #pragma unroll
        for (int k4 = 0; k4 < FDIM / 4; k4++) {
            float2 wv0 = *(const float2*)&Wsh[4*k4 + 0][2 * lane];
            float2 wv1 = *(const float2*)&Wsh[4*k4 + 1][2 * lane];
            float2 wv2 = *(const float2*)&Wsh[4*k4 + 2][2 * lane];
            float2 wv3 = *(const float2*)&Wsh[4*k4 + 3][2 * lane];
            #pragma unroll
            for (int i = 0; i < 4; i++) {
                float4 xv = *(const float4*)&rp[i][4 * k4];   // broadcast LDS.128
                acc[i][0] += xv.x * wv0.x;  acc[i][1] += xv.x * wv0.y;
                acc[i][0] += xv.y * wv1.x;  acc[i][1] += xv.y * wv1.y;
                acc[i][0] += xv.z * wv2.x;  acc[i][1] += xv.z * wv2.y;
                acc[i][0] += xv.w * wv3.x;  acc[i][1] += xv.w * wv3.y;
            }
        }
        // in-place z write: this warp is the only reader/writer of its rows;
        // clamped-row reads by other warps feed only discarded accumulators
        #pragma unroll
        for (int i = 0; i < 4; i++) {
            int rr = base + i;
            if (rr < ROWS)
                *(float2*)&zsh[rr][2 * lane] = make_float2(acc[i][0], acc[i][1]);
        }
        // el/er per row via butterfly reduction
        float el[4], er[4];
        #pragma unroll
        for (int i = 0; i < 4; i++) {
            el[i] = acc[i][0] * alv.x + acc[i][1] * alv.y;
            er[i] = acc[i][0] * arv.x + acc[i][1] * arv.y;
        }
        #pragma unroll
        for (int off = 16; off; off >>= 1) {
            #pragma unroll
            for (int i = 0; i < 4; i++) {
                el[i] += __shfl_xor_sync(0xffffffffu, el[i], off);
                er[i] += __shfl_xor_sync(0xffffffffu, er[i], off);
            }
        }
        if (lane == 0) {
            #pragma unroll
            for (int i = 0; i < 4; i++) {
                int rr = base + i;
                if (rr < ROWS) { elsh[rr] = el[i]; ersh[rr] = er[i]; }
            }
        }
    }
    __syncthreads();

    // ---- attention: dst = last window slot; softmax over 16 src rows ----
    const int g  = tid >> 4;   // 16 groups of 16 lanes
    const int gl = tid & 15;
    const float4 bv = *(const float4*)&bsh[4 * gl];

    for (int j = g; j < BT; j += 16) {
        int t = t0 + j;
        if (t >= T) break;
        float ert = ersh[j + WIN - 1];
        float ew[WIN];
        float m = -1e30f;
        #pragma unroll
        for (int u = 0; u < WIN; u++) {
            float e = elsh[j + u] + ert;
            e = (e > 0.f) ? e : NEG * e;
            ew[u] = e;
            m = fmaxf(m, e);
        }
        float ssum = 0.f;
        #pragma unroll
        for (int u = 0; u < WIN; u++) {
            float x = __expf(ew[u] - m);
            ew[u] = x;
            ssum += x;
        }
        float inv = 1.f / ssum;
        float4 acc = make_float4(0.f, 0.f, 0.f, 0.f);
        #pragma unroll
        for (int u = 0; u < WIN; u++) {
            float4 zv = *(const float4*)&zsh[j + u][4 * gl];
            float w = ew[u];
            acc.x += w * zv.x; acc.y += w * zv.y;
            acc.z += w * zv.z; acc.w += w * zv.w;
        }
        float4 o;
        o.x = acc.x * inv + bv.x;
        o.y = acc.y * inv + bv.y;
        o.z = acc.z * inv + bv.z;
        o.w = acc.w * inv + bv.w;
        *(float4*)&out[(size_t)t * FDIM + 4 * gl] = o;
    }
}

extern "C" void kernel_launch(void* const* d_in, const int* in_sizes, int n_in,
                              void* d_out, int out_size) {
    const float* ori    = (const float*)d_in[0];
    const float* Wfc    = (const float*)d_in[1];
    const float* attn_l = (const float*)d_in[2];
    const float* attn_r = (const float*)d_in[3];
    const float* bias   = (const float*)d_in[4];
    float* out = (float*)d_out;
    int T = in_sizes[0] / FDIM;
    int grid = (T + BT - 1) / BT;
    gat_kernel<<<grid, 256>>>(ori, Wfc, attn_l, attn_r, bias, out, T);
}

// round 8
// speedup vs baseline: 2.2015x; 2.0809x over previous
#include <cuda_runtime.h>

#define F    64
#define WIN  16
#define NEG  0.2f

#define BT1   64
#define ROWS1 (BT1 + WIN - 1)   /* 79 */
#define OPAD  68                /* multiple of 4 for float4 alignment */
#define MPAD  66

#define BT2   128
#define TMAX  100352

__device__ float g_wal[F];
__device__ float g_war[F];
__device__ float g_mixT[(size_t)F * TMAX];   // k-major mixed features

// ---------------- k0: wal = W @ attn_l, war = W @ attn_r ----------------
__global__ void prep_kernel(const float* __restrict__ Wfc,
                            const float* __restrict__ al,
                            const float* __restrict__ ar)
{
    int tid = threadIdx.x;   // 128 threads
    if (tid < F) {
        float s = 0.f;
        for (int o = 0; o < F; o++) s += Wfc[tid * F + o] * al[o];
        g_wal[tid] = s;
    } else if (tid < 2 * F) {
        int f = tid - F;
        float s = 0.f;
        for (int o = 0; o < F; o++) s += Wfc[f * F + o] * ar[o];
        g_war[f] = s;
    }
}

// ---------------- k1: scores + softmax + window mix -> g_mixT ----------------
__global__ __launch_bounds__(256, 3)
void mix_kernel(const float* __restrict__ ori, int T)
{
    __shared__ __align__(16) float orish[ROWS1][OPAD];
    __shared__ __align__(16) float mtx[F][MPAD];   // mixed, transposed [feat][t-local]
    __shared__ float elsh[ROWS1], ersh[ROWS1];

    const int tid = threadIdx.x;
    const int t0  = blockIdx.x * BT1;

    // stage clamped rows + fused score dots (16-lane groups share a row).
    // UNIFORM trip count (5 = ceil(1264/256)) so every shfl is fully populated.
    const int NITEM = ROWS1 * 16;   // 1264
    #pragma unroll
    for (int it = 0; it < (NITEM + 255) / 256; it++) {
        int i0 = tid + it * 256;
        bool valid = i0 < NITEM;
        int i  = valid ? i0 : NITEM - 1;
        int r  = i >> 4;
        int c4 = i & 15;
        int s  = t0 - (WIN - 1) + r;
        s = s < 0 ? 0 : (s > T - 1 ? T - 1 : s);
        float4 xv = ((const float4*)(ori + (size_t)s * F))[c4];
        if (valid) *(float4*)&orish[r][4 * c4] = xv;
        float4 wl = *(const float4*)&g_wal[4 * c4];
        float4 wr = *(const float4*)&g_war[4 * c4];
        float pl = xv.x*wl.x + xv.y*wl.y + xv.z*wl.z + xv.w*wl.w;
        float pr = xv.x*wr.x + xv.y*wr.y + xv.z*wr.z + xv.w*wr.w;
        #pragma unroll
        for (int off = 8; off; off >>= 1) {
            pl += __shfl_xor_sync(0xffffffffu, pl, off);
            pr += __shfl_xor_sync(0xffffffffu, pr, off);
        }
        if (valid && c4 == 0) { elsh[r] = pl; ersh[r] = pr; }
    }
    __syncthreads();

    // softmax over window + mix raw features (linearity: project later)
    const int g  = tid >> 4;
    const int gl = tid & 15;
    for (int j = g; j < BT1; j += 16) {
        float ert = ersh[j + WIN - 1];
        float ew[WIN];
        float m = -1e30f;
        #pragma unroll
        for (int u = 0; u < WIN; u++) {
            float e = elsh[j + u] + ert;
            e = (e > 0.f) ? e : NEG * e;
            ew[u] = e;
            m = fmaxf(m, e);
        }
        float ssum = 0.f;
        #pragma unroll
        for (int u = 0; u < WIN; u++) {
            float x = __expf(ew[u] - m);
            ew[u] = x;
            ssum += x;
        }
        float inv = 1.f / ssum;
        float4 acc = make_float4(0.f, 0.f, 0.f, 0.f);
        #pragma unroll
        for (int u = 0; u < WIN; u++) {
            float4 xv = *(const float4*)&orish[j + u][4 * gl];
            float w = ew[u];
            acc.x += w * xv.x; acc.y += w * xv.y;
            acc.z += w * xv.z; acc.w += w * xv.w;
        }
        // transposed store (feat-major)
        mtx[4 * gl + 0][j] = acc.x * inv;
        mtx[4 * gl + 1][j] = acc.y * inv;
        mtx[4 * gl + 2][j] = acc.z * inv;
        mtx[4 * gl + 3][j] = acc.w * inv;
    }
    __syncthreads();

    // coalesced store to global k-major scratch
    for (int i = tid; i < F * BT1; i += 256) {
        int f = i >> 6, c = i & 63;
        int t = t0 + c;
        if (t < T) g_mixT[(size_t)f * T + t] = mtx[f][c];
    }
}

// ---------------- k2: out = mixed @ W + bias (register-tiled GEMM) ----------------
__global__ __launch_bounds__(256, 3)
void gemm_kernel(const float* __restrict__ Wfc,
                 const float* __restrict__ bias,
                 float* __restrict__ out, int T)
{
    __shared__ __align__(16) float xT[F][BT2];   // 32768 B, k-major x tile
    __shared__ __align__(16) float Wsh[F][F];    // 16384 B  (total = 48 KB exactly)

    const int tid = threadIdx.x;
    const int t0  = blockIdx.x * BT2;

    // stage W
    for (int i = tid; i < F * F / 4; i += 256)
        ((float4*)Wsh)[i] = ((const float4*)Wfc)[i];

    // stage x tile (k-major rows of g_mixT -> contiguous copy)
    if (t0 + BT2 <= T) {
        for (int i = tid; i < F * (BT2 / 4); i += 256) {
            int f = i >> 5, c4 = i & 31;
            *(float4*)&xT[f][4 * c4] =
                *(const float4*)&g_mixT[(size_t)f * T + t0 + 4 * c4];
        }
    } else {
        for (int i = tid; i < F * BT2; i += 256) {
            int f = i >> 7, c = i & 127;
            int t = t0 + c;
            xT[f][c] = (t < T) ? g_mixT[(size_t)f * T + t] : 0.f;
        }
    }
    __syncthreads();

    // frag: thread (lane, warp) -> rows 4*lane..4*lane+3, cols 8*warp..8*warp+7
    const int lane = tid & 31;
    const int wq   = tid >> 5;
    const int r0   = 4 * lane;

    float acc[4][8];
    #pragma unroll
    for (int i = 0; i < 4; i++)
        #pragma unroll
        for (int j = 0; j < 8; j++) acc[i][j] = 0.f;

    #pragma unroll 8
    for (int k = 0; k < F; k++) {
        float4 xv = *(const float4*)&xT[k][r0];       // 512B/warp, conflict-free
        float4 wa = *(const float4*)&Wsh[k][8 * wq];
        float4 wb = *(const float4*)&Wsh[k][8 * wq + 4];
        float xa[4] = {xv.x, xv.y, xv.z, xv.w};
        float wv[8] = {wa.x, wa.y, wa.z, wa.w, wb.x, wb.y, wb.z, wb.w};
        #pragma unroll
        for (int i = 0; i < 4; i++) {
            float x = xa[i];
            #pragma unroll
            for (int j = 0; j < 8; j++) acc[i][j] += x * wv[j];
        }
    }
    __syncthreads();   // all xT reads done -> reuse xT as z-stage [BT2][F] (swizzled)

    float* zst = &xT[0][0];
    #pragma unroll
    for (int i = 0; i < 4; i++) {
        int row = r0 + i;
        int sw  = (lane & 7) << 2;     // xor-swizzle on col bits 2-4 (row>>2 == lane)
        #pragma unroll
        for (int h = 0; h < 2; h++) {
            int col  = 8 * wq + 4 * h;
            int colx = col ^ sw;
            *(float4*)&zst[row * F + colx] =
                make_float4(acc[i][4*h+0], acc[i][4*h+1], acc[i][4*h+2], acc[i][4*h+3]);
        }
    }
    __syncthreads();

    // coalesced epilogue: add bias, store
    for (int i = tid; i < BT2 * 16; i += 256) {
        int row = i >> 4, c4 = i & 15;
        int t = t0 + row;
        if (t >= T) continue;
        int colx = (4 * c4) ^ (((row >> 2) & 7) << 2);
        float4 z = *(const float4*)&zst[row * F + colx];
        float4 b = *(const float4*)&bias[4 * c4];
        z.x += b.x; z.y += b.y; z.z += b.z; z.w += b.w;
        *(float4*)&out[(size_t)t * F + 4 * c4] = z;
    }
}

// ---------------- launch ----------------
extern "C" void kernel_launch(void* const* d_in, const int* in_sizes, int n_in,
                              void* d_out, int out_size) {
    const float* ori  = (const float*)d_in[0];
    const float* Wfc  = (const float*)d_in[1];
    const float* al   = (const float*)d_in[2];
    const float* ar   = (const float*)d_in[3];
    const float* bias = (const float*)d_in[4];
    float* out = (float*)d_out;
    int T = in_sizes[0] / F;

    prep_kernel<<<1, 128>>>(Wfc, al, ar);
    mix_kernel<<<(T + BT1 - 1) / BT1, 256>>>(ori, T);
    gemm_kernel<<<(T + BT2 - 1) / BT2, 256>>>(Wfc, bias, out, T);
}

// round 9
// speedup vs baseline: 2.5116x; 1.1409x over previous
#include <cuda_runtime.h>

#define F    64
#define WIN  16
#define NEG  0.2f
#define BT   64
#define ROWS (BT + WIN - 1)   /* 79 */
#define OPAD 68               /* x-tile pitch  */
#define MTP  68               /* mtx pitch (mult of 4 for aligned float4 reads) */

__global__ __launch_bounds__(256)
void gat_fused(const float* __restrict__ ori,
               const float* __restrict__ Wfc,
               const float* __restrict__ al,
               const float* __restrict__ ar,
               const float* __restrict__ bias,
               float* __restrict__ out, int T)
{
    // uni: first holds x halo tile [ROWS][OPAD], later re-used as mtx [F][MTP]
    __shared__ __align__(16) float uni[ROWS * OPAD];   // 21488 B (>= 64*68*4)
    __shared__ __align__(16) float Wsh[F][F];          // 16384 B
    __shared__ __align__(16) float walsh[F], warsh[F], bsh[F];
    __shared__ __align__(16) float alsh[F],  arsh[F];
    __shared__ float elsh[ROWS], ersh[ROWS];

    const int tid = threadIdx.x;
    const int t0  = blockIdx.x * BT;

    // ---- stage W (row-major [f][o]) + small vectors + clamped x halo ----
    for (int i = tid; i < F * F / 4; i += 256)
        ((float4*)Wsh)[i] = ((const float4*)Wfc)[i];
    if (tid < F) { alsh[tid] = al[tid]; arsh[tid] = ar[tid]; bsh[tid] = bias[tid]; }

    for (int i = tid; i < ROWS * 16; i += 256) {       // no shfl here: ragged loop OK
        int r  = i >> 4;
        int c4 = i & 15;
        int s  = t0 - (WIN - 1) + r;
        s = s < 0 ? 0 : (s > T - 1 ? T - 1 : s);
        *(float4*)&uni[r * OPAD + 4 * c4] = ((const float4*)(ori + (size_t)s * F))[c4];
    }
    __syncthreads();

    // ---- wal = W @ attn_l, war = W @ attn_r  (diagonal smem reads, no conflicts) ----
    if (tid < 2 * F) {
        int  f   = tid & 63;
        bool isl = tid < F;
        const float* av = isl ? alsh : arsh;
        float s = 0.f;
        #pragma unroll 8
        for (int i = 0; i < F; i++) {
            int o = (f + i) & 63;
            s += Wsh[f][o] * av[o];
        }
        if (isl) walsh[f] = s; else warsh[f] = s;
    }
    __syncthreads();

    // ---- scores: el[r]=x[r]*wal, er[r]=x[r]*war; 16-lane groups, UNIFORM trips ----
    #pragma unroll
    for (int it = 0; it < (ROWS * 16 + 255) / 256; it++) {   // 5
        int  i0    = tid + it * 256;
        bool valid = i0 < ROWS * 16;
        int  i     = valid ? i0 : ROWS * 16 - 1;
        int  r     = i >> 4;
        int  c4    = i & 15;
        float4 xv = *(const float4*)&uni[r * OPAD + 4 * c4];
        float4 wl = *(const float4*)&walsh[4 * c4];
        float4 wr = *(const float4*)&warsh[4 * c4];
        float pl = xv.x*wl.x + xv.y*wl.y + xv.z*wl.z + xv.w*wl.w;
        float pr = xv.x*wr.x + xv.y*wr.y + xv.z*wr.z + xv.w*wr.w;
        #pragma unroll
        for (int off = 8; off; off >>= 1) {
            pl += __shfl_xor_sync(0xffffffffu, pl, off);
            pr += __shfl_xor_sync(0xffffffffu, pr, off);
        }
        if (valid && c4 == 0) { elsh[r] = pl; ersh[r] = pr; }
    }
    __syncthreads();

    // ---- softmax + window mix into registers (group g owns j = g+16*it) ----
    const int g  = tid >> 4;
    const int gl = tid & 15;
    float4 mval[4];
    #pragma unroll
    for (int it = 0; it < 4; it++) {
        int j = g + 16 * it;
        float ert = ersh[j + WIN - 1];
        float ew[WIN];
        float m = -1e30f;
        #pragma unroll
        for (int u = 0; u < WIN; u++) {
            float e = elsh[j + u] + ert;
            e = (e > 0.f) ? e : NEG * e;
            ew[u] = e;
            m = fmaxf(m, e);
        }
        float ssum = 0.f;
        #pragma unroll
        for (int u = 0; u < WIN; u++) {
            float x = __expf(ew[u] - m);
            ew[u] = x;
            ssum += x;
        }
        float inv = 1.f / ssum;
        float4 acc = make_float4(0.f, 0.f, 0.f, 0.f);
        #pragma unroll
        for (int u = 0; u < WIN; u++) {
            float4 xv = *(const float4*)&uni[(j + u) * OPAD + 4 * gl];
            float w = ew[u];
            acc.x += w * xv.x; acc.y += w * xv.y;
            acc.z += w * xv.z; acc.w += w * xv.w;
        }
        mval[it] = make_float4(acc.x * inv, acc.y * inv, acc.z * inv, acc.w * inv);
    }
    __syncthreads();   // all halo reads done -> uni becomes mtx [F][MTP] (k-major)

    // ---- transposed store with sub-rotation to spread banks ----
    #pragma unroll
    for (int it = 0; it < 4; it++) {
        int j = g + 16 * it;
        float v[4] = {mval[it].x, mval[it].y, mval[it].z, mval[it].w};
        #pragma unroll
        for (int q = 0; q < 4; q++) {
            int sub = (q + gl) & 3;
            uni[(4 * gl + sub) * MTP + j] = v[sub];
        }
    }
    __syncthreads();

    // ---- GEMM: out[t] = mixed[t] @ W + bias; warp wq -> rows 8wq..+7, lane -> 2 cols
    const int lane = tid & 31;
    const int wq   = tid >> 5;
    float acc[8][2];
    #pragma unroll
    for (int i = 0; i < 8; i++) { acc[i][0] = 0.f; acc[i][1] = 0.f; }

    #pragma unroll 4
    for (int k = 0; k < F; k++) {
        float2 wv = *(const float2*)&Wsh[k][2 * lane];        // 256B/warp, 2wf
        float4 xa = *(const float4*)&uni[k * MTP + 8 * wq];    // broadcast LDS.128
        float4 xb = *(const float4*)&uni[k * MTP + 8 * wq + 4];
        float xr[8] = {xa.x, xa.y, xa.z, xa.w, xb.x, xb.y, xb.z, xb.w};
        #pragma unroll
        for (int i = 0; i < 8; i++) {
            acc[i][0] += xr[i] * wv.x;
            acc[i][1] += xr[i] * wv.y;
        }
    }

    // ---- coalesced epilogue straight from registers ----
    float2 bv = *(const float2*)&bsh[2 * lane];
    #pragma unroll
    for (int i = 0; i < 8; i++) {
        int t = t0 + 8 * wq + i;
        if (t < T) {
            float2 o = make_float2(acc[i][0] + bv.x, acc[i][1] + bv.y);
            *(float2*)&out[(size_t)t * F + 2 * lane] = o;
        }
    }
}

extern "C" void kernel_launch(void* const* d_in, const int* in_sizes, int n_in,
                              void* d_out, int out_size) {
    const float* ori  = (const float*)d_in[0];
    const float* Wfc  = (const float*)d_in[1];
    const float* al   = (const float*)d_in[2];
    const float* ar   = (const float*)d_in[3];
    const float* bias = (const float*)d_in[4];
    float* out = (float*)d_out;
    int T = in_sizes[0] / F;
    gat_fused<<<(T + BT - 1) / BT, 256>>>(ori, Wfc, al, ar, bias, out, T);
}